// round 1
// baseline (speedup 1.0000x reference)
#include <cuda_runtime.h>
#include <cuda_bf16.h>
#include <cstddef>

// Problem constants
#define Bq   2
#define Sq   2048
#define Eq   1024
#define Hq   16
#define Dq   64
#define Mq   (Bq*Sq)          // 4096

// Scratch (no allocations allowed)
__device__ float g_q1[(size_t)Mq*Eq];
__device__ float g_q [(size_t)Mq*Eq];
__device__ float g_v [(size_t)Mq*Eq];
__device__ float g_att[(size_t)Mq*Eq];

// ---------------------------------------------------------------------------
// Tiled SGEMM: C[M,N] = A[M,K] * B(+bias). TB=false: B[k,n] (ldb); TB=true: B[n,k] (ldb).
// BM=BN=128, BK=8, 256 threads, 8x8 per thread.
// ---------------------------------------------------------------------------
template<bool TB>
__global__ void __launch_bounds__(256) sgemm_kernel(
    const float* __restrict__ A, const float* __restrict__ B,
    const float* __restrict__ bias, float* __restrict__ C,
    int M, int N, int K, int lda, int ldb, int ldc)
{
    __shared__ float As[8][128];
    __shared__ float Bs[8][132];   // padded row (keeps float4 stores aligned)

    const int tid = threadIdx.x;
    const int m0 = blockIdx.y * 128;
    const int n0 = blockIdx.x * 128;
    const int ty = tid >> 4;       // 0..15
    const int tx = tid & 15;       // 0..15

    float acc[8][8];
    #pragma unroll
    for (int i = 0; i < 8; i++)
        #pragma unroll
        for (int j = 0; j < 8; j++) acc[i][j] = 0.f;

    for (int k0 = 0; k0 < K; k0 += 8) {
        // load A tile (128x8) transposed into As
        {
            int ar = tid >> 1;
            int ac = (tid & 1) * 4;
            float4 t = *(const float4*)(A + (size_t)(m0 + ar) * lda + k0 + ac);
            As[ac + 0][ar] = t.x;
            As[ac + 1][ar] = t.y;
            As[ac + 2][ar] = t.z;
            As[ac + 3][ar] = t.w;
        }
        // load B tile (8x128)
        if (!TB) {
            int br = tid >> 5;           // 0..7
            int bc = (tid & 31) * 4;     // 0..124
            float4 t = *(const float4*)(B + (size_t)(k0 + br) * ldb + n0 + bc);
            *(float4*)&Bs[br][bc] = t;
        } else {
            int bn = tid >> 1;           // 0..127
            int bk = (tid & 1) * 4;      // 0 or 4
            float4 t = *(const float4*)(B + (size_t)(n0 + bn) * ldb + k0 + bk);
            Bs[bk + 0][bn] = t.x;
            Bs[bk + 1][bn] = t.y;
            Bs[bk + 2][bn] = t.z;
            Bs[bk + 3][bn] = t.w;
        }
        __syncthreads();

        #pragma unroll
        for (int k = 0; k < 8; k++) {
            float a[8], b[8];
            #pragma unroll
            for (int i = 0; i < 8; i++) a[i] = As[k][ty * 8 + i];
            #pragma unroll
            for (int j = 0; j < 8; j++) b[j] = Bs[k][tx * 8 + j];
            #pragma unroll
            for (int i = 0; i < 8; i++)
                #pragma unroll
                for (int j = 0; j < 8; j++)
                    acc[i][j] += a[i] * b[j];
        }
        __syncthreads();
    }

    float bv[8];
    #pragma unroll
    for (int j = 0; j < 8; j++) bv[j] = bias[n0 + tx * 8 + j];

    #pragma unroll
    for (int i = 0; i < 8; i++) {
        size_t row = (size_t)(m0 + ty * 8 + i) * ldc + n0 + tx * 8;
        #pragma unroll
        for (int j = 0; j < 8; j++)
            C[row + j] = acc[i][j] + bv[j];
    }
}

// ---------------------------------------------------------------------------
// Flash attention (fp32, causal): per CTA one 64-query block of one (b,h).
// K side is RAW hidden states split per head; V and Q from scratch buffers.
// 256 threads, 16x16 grid, 4x4 micro-tiles. Dynamic smem.
// ---------------------------------------------------------------------------
#define SD 68   // padded tile row stride (floats)

__global__ void __launch_bounds__(256) attn_kernel(
    const float* __restrict__ x, const float* __restrict__ q,
    const float* __restrict__ v, float* __restrict__ out)
{
    extern __shared__ float sm[];
    float* qs = sm;               // [64][SD]
    float* ks = qs + 64 * SD;     // [64][SD]
    float* vs = ks + 64 * SD;     // [64][SD]
    float* sp = vs + 64 * SD;     // [64][SD]
    float* rm = sp + 64 * SD;     // [64]
    float* rl = rm + 64;          // [64]
    float* ra = rl + 64;          // [64]

    const int tid = threadIdx.x;
    const int qb  = blockIdx.x;          // query block 0..31
    const int bh  = blockIdx.y;          // 0..31
    const int b   = bh / Hq;
    const int h   = bh % Hq;
    const int q0  = qb * 64;

    const float* qbase = q   + ((size_t)(b * Sq + q0)) * Eq + h * Dq;
    const float* xbase = x   + ((size_t)(b * Sq))      * Eq + h * Dq;
    const float* vbase = v   + ((size_t)(b * Sq))      * Eq + h * Dq;
    float*       obase = out + ((size_t)(b * Sq + q0)) * Eq + h * Dq;

    // load Q tile 64x64
    for (int i = tid; i < 64 * 16; i += 256) {
        int r = i >> 4, c4 = (i & 15) << 2;
        float4 t = *(const float4*)(qbase + (size_t)r * Eq + c4);
        qs[r * SD + c4 + 0] = t.x;
        qs[r * SD + c4 + 1] = t.y;
        qs[r * SD + c4 + 2] = t.z;
        qs[r * SD + c4 + 3] = t.w;
    }
    if (tid < 64) { rm[tid] = -1e30f; rl[tid] = 0.f; }

    const int ty = tid >> 4, tx = tid & 15;
    float acc[4][4];
    #pragma unroll
    for (int i = 0; i < 4; i++)
        #pragma unroll
        for (int j = 0; j < 4; j++) acc[i][j] = 0.f;

    const float scale = 0.125f;  // 1/sqrt(64)

    for (int kb = 0; kb <= qb; kb++) {
        const int k0 = kb * 64;
        __syncthreads();   // protect tile reuse from previous iteration
        // load K (raw x) and V tiles
        for (int i = tid; i < 64 * 16; i += 256) {
            int r = i >> 4, c4 = (i & 15) << 2;
            float4 t = *(const float4*)(xbase + (size_t)(k0 + r) * Eq + c4);
            ks[r * SD + c4 + 0] = t.x;
            ks[r * SD + c4 + 1] = t.y;
            ks[r * SD + c4 + 2] = t.z;
            ks[r * SD + c4 + 3] = t.w;
            float4 u = *(const float4*)(vbase + (size_t)(k0 + r) * Eq + c4);
            vs[r * SD + c4 + 0] = u.x;
            vs[r * SD + c4 + 1] = u.y;
            vs[r * SD + c4 + 2] = u.z;
            vs[r * SD + c4 + 3] = u.w;
        }
        __syncthreads();

        // S = Q @ K^T (4x4 per thread)
        float s[4][4];
        #pragma unroll
        for (int i = 0; i < 4; i++)
            #pragma unroll
            for (int j = 0; j < 4; j++) s[i][j] = 0.f;
        for (int d = 0; d < 64; d++) {
            float qr[4], kr[4];
            #pragma unroll
            for (int i = 0; i < 4; i++) qr[i] = qs[(ty * 4 + i) * SD + d];
            #pragma unroll
            for (int j = 0; j < 4; j++) kr[j] = ks[(tx * 4 + j) * SD + d];
            #pragma unroll
            for (int i = 0; i < 4; i++)
                #pragma unroll
                for (int j = 0; j < 4; j++)
                    s[i][j] += qr[i] * kr[j];
        }
        // scaled + causal-masked scores into sp
        #pragma unroll
        for (int i = 0; i < 4; i++) {
            int gq = q0 + ty * 4 + i;
            #pragma unroll
            for (int j = 0; j < 4; j++) {
                int gk = k0 + tx * 4 + j;
                sp[(ty * 4 + i) * SD + tx * 4 + j] =
                    (gk <= gq) ? s[i][j] * scale : -1e30f;
            }
        }
        __syncthreads();

        // online softmax: row r handled by 4 threads (16 cols each)
        {
            int r = tid >> 2, g = tid & 3;
            float mx = -1e30f;
            for (int c = g * 16; c < g * 16 + 16; c++)
                mx = fmaxf(mx, sp[r * SD + c]);
            mx = fmaxf(mx, __shfl_xor_sync(0xffffffffu, mx, 1));
            mx = fmaxf(mx, __shfl_xor_sync(0xffffffffu, mx, 2));
            float mold = rm[r];
            float mnew = fmaxf(mold, mx);
            float alpha = __expf(mold - mnew);
            float sum = 0.f;
            for (int c = g * 16; c < g * 16 + 16; c++) {
                float p = __expf(sp[r * SD + c] - mnew);
                sp[r * SD + c] = p;
                sum += p;
            }
            sum += __shfl_xor_sync(0xffffffffu, sum, 1);
            sum += __shfl_xor_sync(0xffffffffu, sum, 2);
            __syncwarp();
            if (g == 0) {
                rm[r] = mnew;
                rl[r] = rl[r] * alpha + sum;
                ra[r] = alpha;
            }
        }
        __syncthreads();

        // acc = acc*alpha + P @ V
        float al[4];
        #pragma unroll
        for (int i = 0; i < 4; i++) al[i] = ra[ty * 4 + i];
        #pragma unroll
        for (int i = 0; i < 4; i++)
            #pragma unroll
            for (int j = 0; j < 4; j++) acc[i][j] *= al[i];
        for (int kk = 0; kk < 64; kk++) {
            float pr[4], vr[4];
            #pragma unroll
            for (int i = 0; i < 4; i++) pr[i] = sp[(ty * 4 + i) * SD + kk];
            #pragma unroll
            for (int j = 0; j < 4; j++) vr[j] = vs[kk * SD + tx * 4 + j];
            #pragma unroll
            for (int i = 0; i < 4; i++)
                #pragma unroll
                for (int j = 0; j < 4; j++)
                    acc[i][j] += pr[i] * vr[j];
        }
    }

    // epilogue: divide by row sum, write [B,S,E] layout
    #pragma unroll
    for (int i = 0; i < 4; i++) {
        int r = ty * 4 + i;
        float inv = 1.f / rl[r];
        #pragma unroll
        for (int j = 0; j < 4; j++)
            obase[(size_t)r * Eq + tx * 4 + j] = acc[i][j] * inv;
    }
}

// ---------------------------------------------------------------------------
// Launch
// ---------------------------------------------------------------------------
extern "C" void kernel_launch(void* const* d_in, const int* in_sizes, int n_in,
                              void* d_out, int out_size)
{
    const float* x        = (const float*)d_in[0];   // [B,S,E]
    const float* c_attn_w = (const float*)d_in[1];   // [E, 3E]
    const float* c_attn_b = (const float*)d_in[2];   // [3E]
    const float* c_proj_w = (const float*)d_in[3];   // [E, E]
    const float* c_proj_b = (const float*)d_in[4];   // [E]
    float* out = (float*)d_out;                      // [B,S,E]

    float *q1, *q, *v, *att;
    cudaGetSymbolAddress((void**)&q1,  g_q1);
    cudaGetSymbolAddress((void**)&q,   g_q);
    cudaGetSymbolAddress((void**)&v,   g_v);
    cudaGetSymbolAddress((void**)&att, g_att);

    const int M = Mq, N = Eq, K = Eq;
    dim3 ggrid(N / 128, M / 128);   // (8, 32)
    dim3 gblk(256);

    // q1 = x @ Wq + bq   (Wq = c_attn_w[:, 0:E], ldb = 3E)
    sgemm_kernel<false><<<ggrid, gblk>>>(x, c_attn_w, c_attn_b, q1,
                                         M, N, K, Eq, 3 * Eq, Eq);
    // v = x @ Wv + bv    (Wv = c_attn_w[:, 2E:3E])
    sgemm_kernel<false><<<ggrid, gblk>>>(x, c_attn_w + 2 * Eq, c_attn_b + 2 * Eq, v,
                                         M, N, K, Eq, 3 * Eq, Eq);
    // q = q1 @ Wk^T + bk  (Wk rows at c_attn_w[n*3E + E + k])
    sgemm_kernel<true><<<ggrid, gblk>>>(q1, c_attn_w + Eq, c_attn_b + Eq, q,
                                        M, N, K, Eq, 3 * Eq, Eq);

    // flash attention (causal), K side = raw x
    static int smem_set = 0;
    const int smem_bytes = (4 * 64 * SD + 3 * 64) * (int)sizeof(float); // 70400
    if (!smem_set) {
        cudaFuncSetAttribute(attn_kernel,
                             cudaFuncAttributeMaxDynamicSharedMemorySize, smem_bytes);
        smem_set = 1;
    }
    dim3 agrid(Sq / 64, Bq * Hq);   // (32, 32)
    attn_kernel<<<agrid, 256, smem_bytes>>>(x, q, v, att);

    // out = att @ c_proj_w + c_proj_b
    sgemm_kernel<false><<<ggrid, gblk>>>(att, c_proj_w, c_proj_b, out,
                                         M, N, K, Eq, Eq, Eq);
}

// round 2
// speedup vs baseline: 2.4185x; 2.4185x over previous
#include <cuda_runtime.h>
#include <cstddef>
#include <cstdint>

// Problem constants
#define Bq   2
#define Sq   2048
#define Eq   1024
#define Hq   16
#define Dq   64
#define Mq   (Bq*Sq)          // 4096

// Scratch (no allocations allowed)
__device__ float g_q1[(size_t)Mq*Eq];
__device__ float g_q [(size_t)Mq*Eq];
__device__ float g_v [(size_t)Mq*Eq];
__device__ float g_att[(size_t)Mq*Eq];

// ---------------------------------------------------------------------------
// TF32 helpers
// ---------------------------------------------------------------------------
__device__ __forceinline__ unsigned f2tf(float x) {
    unsigned r;
    asm("cvt.rna.tf32.f32 %0, %1;" : "=r"(r) : "f"(x));
    return r;
}

__device__ __forceinline__ void mma_tf32(float* c, const unsigned* a, const unsigned* b) {
    asm volatile(
        "mma.sync.aligned.m16n8k8.row.col.f32.tf32.tf32.f32 "
        "{%0,%1,%2,%3}, {%4,%5,%6,%7}, {%8,%9}, {%0,%1,%2,%3};"
        : "+f"(c[0]), "+f"(c[1]), "+f"(c[2]), "+f"(c[3])
        : "r"(a[0]), "r"(a[1]), "r"(a[2]), "r"(a[3]),
          "r"(b[0]), "r"(b[1]));
}

// ---------------------------------------------------------------------------
// TF32 tensor-core GEMM: C[M,N] = A[M,K] @ B (+bias), M=4096, N=K=1024.
// TB=false: B[k][n] with leading dim ldb. TB=true: B[n][k] with leading dim ldb.
// Tile 128x128x32, 256 threads = 8 warps (2 x 4), warp tile 64x32.
// Smem holds tiles in *fragment order*: As[ks][mfrag][lane][4], Bs[ks][nfrag][lane][2].
// ---------------------------------------------------------------------------
template<bool TB>
__global__ void __launch_bounds__(256, 1) gemm_tc(
    const float* __restrict__ A, const float* __restrict__ B,
    const float* __restrict__ bias, float* __restrict__ C,
    int lda, int ldb, int ldc)
{
    extern __shared__ unsigned sh[];
    unsigned* As = sh;              // 2 bufs x 4096 (4 ks * 8 mfrag * 32 * 4)
    unsigned* Bs = sh + 2 * 4096;   // 2 bufs x 4096 (4 ks * 16 nfrag * 32 * 2)

    const int tid  = threadIdx.x;
    const int lane = tid & 31;
    const int wid  = tid >> 5;
    const int wm   = wid & 1;       // 0..1  (64 rows each)
    const int wn   = wid >> 1;      // 0..3  (32 cols each)
    const int g    = lane >> 2;
    const int tig  = lane & 3;
    const int m0   = blockIdx.y * 128;
    const int n0   = blockIdx.x * 128;
    const int NT   = 1024 / 32;

    float acc[4][4][4];
    #pragma unroll
    for (int mi = 0; mi < 4; mi++)
        #pragma unroll
        for (int ni = 0; ni < 4; ni++)
            #pragma unroll
            for (int r = 0; r < 4; r++) acc[mi][ni][r] = 0.f;

    float regA[16], regB[16];

    // --- loaders: gmem -> regs ---
    auto ldA = [&](int k0) {
        #pragma unroll
        for (int i = 0; i < 4; i++) {
            int f = tid + i * 256;            // 128 rows x 8 float4 cols
            int m = f >> 3, c4 = (f & 7) << 2;
            float4 t = *(const float4*)(A + (size_t)(m0 + m) * lda + k0 + c4);
            regA[i*4+0] = t.x; regA[i*4+1] = t.y; regA[i*4+2] = t.z; regA[i*4+3] = t.w;
        }
    };
    auto ldB = [&](int k0) {
        if (!TB) {
            #pragma unroll
            for (int i = 0; i < 4; i++) {
                int f = tid + i * 256;        // 32 k-rows x 32 float4 cols
                int k = f >> 5, nc4 = (f & 31) << 2;
                float4 t = *(const float4*)(B + (size_t)(k0 + k) * ldb + n0 + nc4);
                regB[i*4+0] = t.x; regB[i*4+1] = t.y; regB[i*4+2] = t.z; regB[i*4+3] = t.w;
            }
        } else {
            #pragma unroll
            for (int i = 0; i < 4; i++) {
                int f = tid + i * 256;        // 128 n-rows x 8 float4 cols
                int n = f >> 3, kc4 = (f & 7) << 2;
                float4 t = *(const float4*)(B + (size_t)(n0 + n) * ldb + k0 + kc4);
                regB[i*4+0] = t.x; regB[i*4+1] = t.y; regB[i*4+2] = t.z; regB[i*4+3] = t.w;
            }
        }
    };

    // --- regs -> smem (fragment order, with tf32 conversion) ---
    auto stA = [&](int buf) {
        unsigned* dst = As + buf * 4096;
        #pragma unroll
        for (int i = 0; i < 4; i++) {
            int f = tid + i * 256;
            int m = f >> 3, c4 = (f & 7) << 2;
            int mfrag = m >> 4;
            int mhalf = ((m & 15) >= 8) ? 1 : 0;
            int lbase = (m & 7) * 4;
            #pragma unroll
            for (int j = 0; j < 4; j++) {
                int k  = c4 + j;
                int ks = k >> 3, klo = k & 7;
                int ln = lbase + (klo & 3);
                int rg = mhalf + ((klo >= 4) ? 2 : 0);
                dst[((ks * 8 + mfrag) * 32 + ln) * 4 + rg] = f2tf(regA[i*4+j]);
            }
        }
    };
    auto stB = [&](int buf) {
        unsigned* dst = Bs + buf * 4096;
        if (!TB) {
            #pragma unroll
            for (int i = 0; i < 4; i++) {
                int f = tid + i * 256;
                int k = f >> 5, nc4 = (f & 31) << 2;
                int ks = k >> 3, klo = k & 7;
                int rg = (klo >= 4) ? 1 : 0;
                #pragma unroll
                for (int j = 0; j < 4; j++) {
                    int n = nc4 + j;
                    int nf = n >> 3;
                    int ln = (n & 7) * 4 + (klo & 3);
                    dst[((ks * 16 + nf) * 32 + ln) * 2 + rg] = f2tf(regB[i*4+j]);
                }
            }
        } else {
            #pragma unroll
            for (int i = 0; i < 4; i++) {
                int f = tid + i * 256;
                int n = f >> 3, kc4 = (f & 7) << 2;
                int nf = n >> 3;
                int lpart = (n & 7) * 4;
                #pragma unroll
                for (int j = 0; j < 4; j++) {
                    int k  = kc4 + j;
                    int ks = k >> 3, klo = k & 7;
                    int ln = lpart + (klo & 3);
                    int rg = (klo >= 4) ? 1 : 0;
                    dst[((ks * 16 + nf) * 32 + ln) * 2 + rg] = f2tf(regB[i*4+j]);
                }
            }
        }
    };

    auto compute = [&](int buf) {
        const unsigned* as = As + buf * 4096;
        const unsigned* bs = Bs + buf * 4096;
        #pragma unroll
        for (int ks = 0; ks < 4; ks++) {
            unsigned af[4][4], bf[4][2];
            #pragma unroll
            for (int mi = 0; mi < 4; mi++) {
                uint4 t = *(const uint4*)(as + ((ks * 8 + wm * 4 + mi) * 32 + lane) * 4);
                af[mi][0] = t.x; af[mi][1] = t.y; af[mi][2] = t.z; af[mi][3] = t.w;
            }
            #pragma unroll
            for (int ni = 0; ni < 4; ni++) {
                uint2 t = *(const uint2*)(bs + ((ks * 16 + wn * 4 + ni) * 32 + lane) * 2);
                bf[ni][0] = t.x; bf[ni][1] = t.y;
            }
            #pragma unroll
            for (int mi = 0; mi < 4; mi++)
                #pragma unroll
                for (int ni = 0; ni < 4; ni++)
                    mma_tf32(acc[mi][ni], af[mi], bf[ni]);
        }
    };

    // pipeline: prefetch next tile to regs during compute of current
    ldA(0); ldB(0);
    stA(0); stB(0);
    __syncthreads();

    for (int it = 0; it < NT; ++it) {
        int buf = it & 1;
        if (it + 1 < NT) { ldA((it + 1) * 32); ldB((it + 1) * 32); }
        compute(buf);
        if (it + 1 < NT) {
            __syncthreads();
            stA(buf ^ 1); stB(buf ^ 1);
            __syncthreads();
        }
    }

    // epilogue + bias
    #pragma unroll
    for (int ni = 0; ni < 4; ni++) {
        int col = n0 + wn * 32 + ni * 8 + 2 * tig;
        float b0 = bias[col], b1 = bias[col + 1];
        #pragma unroll
        for (int mi = 0; mi < 4; mi++) {
            int row = m0 + wm * 64 + mi * 16 + g;
            float2 v0 = make_float2(acc[mi][ni][0] + b0, acc[mi][ni][1] + b1);
            float2 v1 = make_float2(acc[mi][ni][2] + b0, acc[mi][ni][3] + b1);
            *(float2*)(C + (size_t)row * ldc + col)       = v0;
            *(float2*)(C + (size_t)(row + 8) * ldc + col) = v1;
        }
    }
}

// ---------------------------------------------------------------------------
// TF32 tensor-core flash attention (causal). Per CTA: 128 q rows of one (b,h).
// 8 warps x 16 q rows. Q fragments register-resident; K/V tiles (64 x 64)
// staged in fragment-order smem; S kept in registers; online softmax in regs;
// P C-frag -> A-frag via shfl (no smem round trip).
// ---------------------------------------------------------------------------
__global__ void __launch_bounds__(256, 1) attn_tc(
    const float* __restrict__ x, const float* __restrict__ q,
    const float* __restrict__ v, float* __restrict__ out)
{
    extern __shared__ unsigned sh[];
    unsigned* Ks = sh;          // [8 ks(d)] [8 nf(kpos)] [32] [2] = 4096
    unsigned* Vs = sh + 4096;   // [8 ks(kpos)] [8 nf(d)] [32] [2] = 4096

    const int tid  = threadIdx.x;
    const int lane = tid & 31;
    const int wid  = tid >> 5;
    const int g    = lane >> 2;
    const int tig  = lane & 3;

    const int qb = blockIdx.x;           // 0..15
    const int bh = blockIdx.y;           // 0..31
    const int b  = bh >> 4;
    const int h  = bh & 15;
    const int q0 = qb * 128;

    const float* qbase = q   + ((size_t)(b * Sq + q0)) * Eq + h * Dq;
    const float* xbase = x   + ((size_t)(b * Sq))      * Eq + h * Dq;
    const float* vbase = v   + ((size_t)(b * Sq))      * Eq + h * Dq;
    float*       obase = out + ((size_t)(b * Sq + q0)) * Eq + h * Dq;

    // Q fragments (scaled by 1/sqrt(D)=0.125 before tf32 rounding)
    unsigned qa[8][4];
    {
        const float* qr0 = qbase + (size_t)(wid * 16 + g) * Eq;
        const float* qr1 = qr0 + (size_t)8 * Eq;
        #pragma unroll
        for (int ks = 0; ks < 8; ks++) {
            int c = ks * 8 + tig;
            qa[ks][0] = f2tf(qr0[c]     * 0.125f);
            qa[ks][1] = f2tf(qr1[c]     * 0.125f);
            qa[ks][2] = f2tf(qr0[c + 4] * 0.125f);
            qa[ks][3] = f2tf(qr1[c + 4] * 0.125f);
        }
    }

    float o[8][4];
    #pragma unroll
    for (int nf = 0; nf < 8; nf++)
        #pragma unroll
        for (int r = 0; r < 4; r++) o[nf][r] = 0.f;

    float m0v = -1e30f, m1v = -1e30f, l0 = 0.f, l1 = 0.f;
    const int row0 = q0 + wid * 16 + g;
    const int NT   = 2 * qb + 2;         // K tiles of 64

    for (int kt = 0; kt < NT; kt++) {
        const int k0 = kt * 64;
        __syncthreads();   // previous tile fully consumed

        // load K (raw x) and V tiles into fragment-order smem, tf32-converted
        #pragma unroll
        for (int i = 0; i < 4; i++) {
            int f  = tid + i * 256;            // 64 kpos x 16 float4(d)
            int kp = f >> 4, dc4 = (f & 15) << 2;
            float4 t = *(const float4*)(xbase + (size_t)(k0 + kp) * Eq + dc4);
            float4 u = *(const float4*)(vbase + (size_t)(k0 + kp) * Eq + dc4);
            float tv[4] = {t.x, t.y, t.z, t.w};
            float uv[4] = {u.x, u.y, u.z, u.w};
            #pragma unroll
            for (int j = 0; j < 4; j++) {
                int d = dc4 + j;
                // K as B-frag of S=Q@K^T: ks=d/8, nf=kp/8
                Ks[(((d >> 3) * 8 + (kp >> 3)) * 32 + (kp & 7) * 4 + (d & 3)) * 2
                   + (((d & 7) >= 4) ? 1 : 0)] = f2tf(tv[j]);
                // V as B-frag of O=P@V: ks=kp/8, nf=d/8
                Vs[(((kp >> 3) * 8 + (d >> 3)) * 32 + (d & 7) * 4 + (kp & 3)) * 2
                   + (((kp & 7) >= 4) ? 1 : 0)] = f2tf(uv[j]);
            }
        }
        __syncthreads();

        // S = Q @ K^T  (warp: 16 x 64)
        float s[8][4];
        #pragma unroll
        for (int nf = 0; nf < 8; nf++)
            #pragma unroll
            for (int r = 0; r < 4; r++) s[nf][r] = 0.f;

        #pragma unroll
        for (int ks = 0; ks < 8; ks++) {
            #pragma unroll
            for (int nf = 0; nf < 8; nf++) {
                uint2 bt = *(const uint2*)(Ks + ((ks * 8 + nf) * 32 + lane) * 2);
                unsigned bf[2] = {bt.x, bt.y};
                mma_tf32(s[nf], qa[ks], bf);
            }
        }

        // causal mask (only the two diagonal tiles ever need it)
        if (k0 + 63 > row0) {
            #pragma unroll
            for (int nf = 0; nf < 8; nf++) {
                int col = k0 + nf * 8 + 2 * tig;
                if (col     > row0)     s[nf][0] = -1e30f;
                if (col + 1 > row0)     s[nf][1] = -1e30f;
                if (col     > row0 + 8) s[nf][2] = -1e30f;
                if (col + 1 > row0 + 8) s[nf][3] = -1e30f;
            }
        }

        // online softmax in registers (rows row0 / row0+8 per thread)
        float mx0 = -1e30f, mx1 = -1e30f;
        #pragma unroll
        for (int nf = 0; nf < 8; nf++) {
            mx0 = fmaxf(mx0, fmaxf(s[nf][0], s[nf][1]));
            mx1 = fmaxf(mx1, fmaxf(s[nf][2], s[nf][3]));
        }
        mx0 = fmaxf(mx0, __shfl_xor_sync(0xffffffffu, mx0, 1));
        mx0 = fmaxf(mx0, __shfl_xor_sync(0xffffffffu, mx0, 2));
        mx1 = fmaxf(mx1, __shfl_xor_sync(0xffffffffu, mx1, 1));
        mx1 = fmaxf(mx1, __shfl_xor_sync(0xffffffffu, mx1, 2));

        float mn0 = fmaxf(m0v, mx0), mn1 = fmaxf(m1v, mx1);
        float a0 = __expf(m0v - mn0), a1 = __expf(m1v - mn1);
        m0v = mn0; m1v = mn1;

        float sum0 = 0.f, sum1 = 0.f;
        #pragma unroll
        for (int nf = 0; nf < 8; nf++) {
            s[nf][0] = __expf(s[nf][0] - mn0); sum0 += s[nf][0];
            s[nf][1] = __expf(s[nf][1] - mn0); sum0 += s[nf][1];
            s[nf][2] = __expf(s[nf][2] - mn1); sum1 += s[nf][2];
            s[nf][3] = __expf(s[nf][3] - mn1); sum1 += s[nf][3];
        }
        sum0 += __shfl_xor_sync(0xffffffffu, sum0, 1);
        sum0 += __shfl_xor_sync(0xffffffffu, sum0, 2);
        sum1 += __shfl_xor_sync(0xffffffffu, sum1, 1);
        sum1 += __shfl_xor_sync(0xffffffffu, sum1, 2);
        l0 = l0 * a0 + sum0;
        l1 = l1 * a1 + sum1;

        #pragma unroll
        for (int nf = 0; nf < 8; nf++) {
            o[nf][0] *= a0; o[nf][1] *= a0;
            o[nf][2] *= a1; o[nf][3] *= a1;
        }

        // O += P @ V ; P C-frags -> A-frags via shfl
        const int src1 = g * 4 + (tig >> 1);
        const int src2 = src1 + 2;
        #pragma unroll
        for (int ks = 0; ks < 8; ks++) {
            float w0 = __shfl_sync(0xffffffffu, s[ks][0], src1);
            float w1 = __shfl_sync(0xffffffffu, s[ks][1], src1);
            float w2 = __shfl_sync(0xffffffffu, s[ks][2], src1);
            float w3 = __shfl_sync(0xffffffffu, s[ks][3], src1);
            float y0 = __shfl_sync(0xffffffffu, s[ks][0], src2);
            float y1 = __shfl_sync(0xffffffffu, s[ks][1], src2);
            float y2 = __shfl_sync(0xffffffffu, s[ks][2], src2);
            float y3 = __shfl_sync(0xffffffffu, s[ks][3], src2);
            unsigned pa[4];
            pa[0] = f2tf((tig & 1) ? w1 : w0);
            pa[1] = f2tf((tig & 1) ? w3 : w2);
            pa[2] = f2tf((tig & 1) ? y1 : y0);
            pa[3] = f2tf((tig & 1) ? y3 : y2);
            #pragma unroll
            for (int nf = 0; nf < 8; nf++) {
                uint2 bt = *(const uint2*)(Vs + ((ks * 8 + nf) * 32 + lane) * 2);
                unsigned bf[2] = {bt.x, bt.y};
                mma_tf32(o[nf], pa, bf);
            }
        }
    }

    // epilogue: normalize and store
    float il0 = 1.f / l0, il1 = 1.f / l1;
    #pragma unroll
    for (int nf = 0; nf < 8; nf++) {
        int col = nf * 8 + 2 * tig;
        float* p0 = obase + (size_t)(wid * 16 + g) * Eq + col;
        float* p1 = p0 + (size_t)8 * Eq;
        *(float2*)p0 = make_float2(o[nf][0] * il0, o[nf][1] * il0);
        *(float2*)p1 = make_float2(o[nf][2] * il1, o[nf][3] * il1);
    }
}

// ---------------------------------------------------------------------------
// Launch
// ---------------------------------------------------------------------------
extern "C" void kernel_launch(void* const* d_in, const int* in_sizes, int n_in,
                              void* d_out, int out_size)
{
    const float* x        = (const float*)d_in[0];   // [B,S,E]
    const float* c_attn_w = (const float*)d_in[1];   // [E, 3E]
    const float* c_attn_b = (const float*)d_in[2];   // [3E]
    const float* c_proj_w = (const float*)d_in[3];   // [E, E]
    const float* c_proj_b = (const float*)d_in[4];   // [E]
    float* out = (float*)d_out;                      // [B,S,E]

    float *q1, *q, *v, *att;
    cudaGetSymbolAddress((void**)&q1,  g_q1);
    cudaGetSymbolAddress((void**)&q,   g_q);
    cudaGetSymbolAddress((void**)&v,   g_v);
    cudaGetSymbolAddress((void**)&att, g_att);

    const int gemm_smem = 4 * 4096 * 4;   // 64 KB
    const int attn_smem = 2 * 4096 * 4;   // 32 KB
    static int attr_set = 0;
    if (!attr_set) {
        cudaFuncSetAttribute(gemm_tc<false>,
                             cudaFuncAttributeMaxDynamicSharedMemorySize, gemm_smem);
        cudaFuncSetAttribute(gemm_tc<true>,
                             cudaFuncAttributeMaxDynamicSharedMemorySize, gemm_smem);
        cudaFuncSetAttribute(attn_tc,
                             cudaFuncAttributeMaxDynamicSharedMemorySize, attn_smem);
        attr_set = 1;
    }

    dim3 ggrid(Eq / 128, Mq / 128);   // (8, 32)

    // q1 = x @ Wq + bq
    gemm_tc<false><<<ggrid, 256, gemm_smem>>>(x, c_attn_w, c_attn_b, q1,
                                              Eq, 3 * Eq, Eq);
    // v = x @ Wv + bv
    gemm_tc<false><<<ggrid, 256, gemm_smem>>>(x, c_attn_w + 2 * Eq, c_attn_b + 2 * Eq, v,
                                              Eq, 3 * Eq, Eq);
    // q = q1 @ Wk^T + bk   (Wk rows at (c_attn_w + Eq)[n*3E + k])
    gemm_tc<true><<<ggrid, 256, gemm_smem>>>(q1, c_attn_w + Eq, c_attn_b + Eq, q,
                                             Eq, 3 * Eq, Eq);

    // flash attention (causal), K side = raw x
    dim3 agrid(Sq / 128, Bq * Hq);    // (16, 32)
    attn_tc<<<agrid, 256, attn_smem>>>(x, q, v, att);

    // out = att @ c_proj_w + c_proj_b
    gemm_tc<false><<<ggrid, 256, gemm_smem>>>(att, c_proj_w, c_proj_b, out,
                                              Eq, Eq, Eq);
}

// round 3
// speedup vs baseline: 5.9861x; 2.4751x over previous
#include <cuda_runtime.h>
#include <cstddef>
#include <cstdint>

// Problem constants
#define Bq   2
#define Sq   2048
#define Eq   1024
#define Hq   16
#define Dq   64
#define Mq   (Bq*Sq)          // 4096

// ---------------------------------------------------------------------------
// Scratch (device globals; no allocations allowed)
// ---------------------------------------------------------------------------
__device__ float    g_q1 [(size_t)Mq*Eq];
__device__ float    g_q  [(size_t)Mq*Eq];
__device__ float    g_v  [(size_t)Mq*Eq];
__device__ float    g_att[(size_t)Mq*Eq];

// fragment-order tf32 copies
__device__ unsigned g_xA  [(size_t)Mq*Eq];    // x as GEMM-A frags
__device__ unsigned g_q1A [(size_t)Mq*Eq];    // q1 as GEMM-A frags
__device__ unsigned g_attA[(size_t)Mq*Eq];    // att as GEMM-A frags
__device__ unsigned g_wqB [(size_t)Eq*Eq];    // Wq  as GEMM-B frags
__device__ unsigned g_wvB [(size_t)Eq*Eq];    // Wv  as GEMM-B frags
__device__ unsigned g_wkB [(size_t)Eq*Eq];    // Wk^T as GEMM-B frags
__device__ unsigned g_wpB [(size_t)Eq*Eq];    // Wproj as GEMM-B frags
__device__ unsigned g_xK  [(size_t)Mq*Eq];    // x as attention-K frags
__device__ unsigned g_vV  [(size_t)Mq*Eq];    // v as attention-V frags

// ---------------------------------------------------------------------------
// helpers
// ---------------------------------------------------------------------------
__device__ __forceinline__ unsigned f2tf(float x) {
    unsigned r;
    asm("cvt.rna.tf32.f32 %0, %1;" : "=r"(r) : "f"(x));
    return r;
}
__device__ __forceinline__ void mma_tf32(float* c, const unsigned* a, const unsigned* b) {
    asm volatile(
        "mma.sync.aligned.m16n8k8.row.col.f32.tf32.tf32.f32 "
        "{%0,%1,%2,%3}, {%4,%5,%6,%7}, {%8,%9}, {%0,%1,%2,%3};"
        : "+f"(c[0]), "+f"(c[1]), "+f"(c[2]), "+f"(c[3])
        : "r"(a[0]), "r"(a[1]), "r"(a[2]), "r"(a[3]),
          "r"(b[0]), "r"(b[1]));
}
__device__ __forceinline__ void cpasync16(uint32_t s, const void* g) {
    asm volatile("cp.async.cg.shared.global [%0], [%1], 16;" :: "r"(s), "l"(g));
}
__device__ __forceinline__ void cp_commit() {
    asm volatile("cp.async.commit_group;");
}

// ---------------------------------------------------------------------------
// Conversion kernels (fp32 -> tf32 fragment-order tiles)
// A-frag tile (128m x 32k): idx = ((ks*8+mfrag)*32 + ln)*4 + rg, 4096 uints.
// B-frag tile (32k x 128n): idx = ((ks*16+nf)*32 + ln)*2 + rg, 4096 uints.
// ---------------------------------------------------------------------------
__global__ void convA(const float* __restrict__ A, unsigned* __restrict__ dst)
{
    // M=4096, K=lda=1024; one thread per float4 along k
    int idx = blockIdx.x * 256 + threadIdx.x;     // 0 .. 4096*256-1
    int m   = idx >> 8;
    int k4  = (idx & 255) << 2;
    float4 t = *(const float4*)(A + (size_t)m * Eq + k4);
    float tv[4] = {t.x, t.y, t.z, t.w};
    int mblk  = m >> 7, mr = m & 127;
    int mfrag = mr >> 4;
    int mhalf = ((mr & 15) >= 8) ? 1 : 0;
    int lbase = (mr & 7) * 4;
    unsigned* tile = dst + ((size_t)mblk * 32 + (k4 >> 5)) * 4096;
    #pragma unroll
    for (int j = 0; j < 4; j++) {
        int k = k4 + j;
        int ks = (k >> 3) & 3, klo = k & 7;
        int ln = lbase + (klo & 3);
        int rg = mhalf + ((klo >= 4) ? 2 : 0);
        tile[((ks * 8 + mfrag) * 32 + ln) * 4 + rg] = f2tf(tv[j]);
    }
}

__global__ void convB(const float* __restrict__ B, unsigned* __restrict__ dst, int ldb)
{
    // B[k][n], K=N=1024; one thread per float4 along n
    int idx = blockIdx.x * 256 + threadIdx.x;     // 0 .. 1024*256-1
    int k   = idx >> 8;
    int n4  = (idx & 255) << 2;
    float4 t = *(const float4*)(B + (size_t)k * ldb + n4);
    float tv[4] = {t.x, t.y, t.z, t.w};
    int ks = (k >> 3) & 3, klo = k & 7;
    int rg = (klo >= 4) ? 1 : 0;
    #pragma unroll
    for (int j = 0; j < 4; j++) {
        int n = n4 + j;
        int nblk = n >> 7;
        int nf   = (n >> 3) & 15;
        int ln   = (n & 7) * 4 + (klo & 3);
        unsigned* tile = dst + ((size_t)nblk * 32 + (k >> 5)) * 4096;
        tile[((ks * 16 + nf) * 32 + ln) * 2 + rg] = f2tf(tv[j]);
    }
}

__global__ void convBT(const float* __restrict__ B, unsigned* __restrict__ dst, int ldb)
{
    // B[n][k] (transposed use), K=N=1024; one thread per float4 along k
    int idx = blockIdx.x * 256 + threadIdx.x;
    int n   = idx >> 8;
    int k4  = (idx & 255) << 2;
    float4 t = *(const float4*)(B + (size_t)n * ldb + k4);
    float tv[4] = {t.x, t.y, t.z, t.w};
    int nblk = n >> 7;
    int nf   = (n >> 3) & 15;
    int lpart = (n & 7) * 4;
    #pragma unroll
    for (int j = 0; j < 4; j++) {
        int k = k4 + j;
        int ks = (k >> 3) & 3, klo = k & 7;
        int ln = lpart + (klo & 3);
        int rg = (klo >= 4) ? 1 : 0;
        unsigned* tile = dst + ((size_t)nblk * 32 + (k >> 5)) * 4096;
        tile[((ks * 16 + nf) * 32 + ln) * 2 + rg] = f2tf(tv[j]);
    }
}

// attention K-frag layout: tile[(b*H+h)*32 + kt], within tile:
//   (((d>>3)*8 + (kp>>3))*32 + (kp&7)*4 + (d&3))*2 + ((d&7)>=4)
__global__ void convAttnK(const float* __restrict__ x, unsigned* __restrict__ dst)
{
    int idx = blockIdx.x * 256 + threadIdx.x;    // B*S*E/4 threads
    int e4 = (idx & 255) << 2;                   // E/4 = 256
    int s  = (idx >> 8) & (Sq - 1);
    int b  = idx >> 19;                          // / (Sq*256)
    float4 t = *(const float4*)(x + ((size_t)(b * Sq + s)) * Eq + e4);
    float tv[4] = {t.x, t.y, t.z, t.w};
    int h  = e4 >> 6;
    int d4 = e4 & 63;
    int kt = s >> 6, kp = s & 63;
    unsigned* tile = dst + (((size_t)(b * Hq + h)) * 32 + kt) * 4096;
    #pragma unroll
    for (int j = 0; j < 4; j++) {
        int d = d4 + j;
        tile[(((d >> 3) * 8 + (kp >> 3)) * 32 + (kp & 7) * 4 + (d & 3)) * 2
             + (((d & 7) >= 4) ? 1 : 0)] = f2tf(tv[j]);
    }
}

// attention V-frag layout: within tile:
//   (((kp>>3)*8 + (d>>3))*32 + (d&7)*4 + (kp&3))*2 + ((kp&7)>=4)
__global__ void convAttnV(const float* __restrict__ v, unsigned* __restrict__ dst)
{
    int idx = blockIdx.x * 256 + threadIdx.x;
    int e4 = (idx & 255) << 2;
    int s  = (idx >> 8) & (Sq - 1);
    int b  = idx >> 19;
    float4 t = *(const float4*)(v + ((size_t)(b * Sq + s)) * Eq + e4);
    float tv[4] = {t.x, t.y, t.z, t.w};
    int h  = e4 >> 6;
    int d4 = e4 & 63;
    int kt = s >> 6, kp = s & 63;
    unsigned* tile = dst + (((size_t)(b * Hq + h)) * 32 + kt) * 4096;
    int rg = ((kp & 7) >= 4) ? 1 : 0;
    #pragma unroll
    for (int j = 0; j < 4; j++) {
        int d = d4 + j;
        tile[(((kp >> 3) * 8 + (d >> 3)) * 32 + (d & 7) * 4 + (kp & 3)) * 2 + rg]
            = f2tf(tv[j]);
    }
}

// ---------------------------------------------------------------------------
// GEMM v3: C[4096,1024] = Afrag @ Bfrag (+bias). Tiles pre-converted tf32.
// CTA 128x128x32, 3-stage cp.async pipeline, warp tile 64x32.
// ---------------------------------------------------------------------------
__global__ void __launch_bounds__(256, 2) gemm_frag(
    const unsigned* __restrict__ Afrag, const unsigned* __restrict__ Bfrag,
    const float* __restrict__ bias, float* __restrict__ C)
{
    extern __shared__ unsigned sh[];              // 3 * 8192 uints = 96 KB
    const int tid  = threadIdx.x;
    const int lane = tid & 31;
    const int wid  = tid >> 5;
    const int wm   = wid & 1;
    const int wn   = wid >> 1;
    const int g    = lane >> 2;
    const int tig  = lane & 3;
    const int m0   = blockIdx.y * 128;
    const int n0   = blockIdx.x * 128;

    const unsigned* gA = Afrag + (size_t)blockIdx.y * 32 * 4096;
    const unsigned* gB = Bfrag + (size_t)blockIdx.x * 32 * 4096;
    const uint32_t sbase = (uint32_t)__cvta_generic_to_shared(sh);

    auto issue = [&](int kt) {
        int st = kt % 3;
        uint32_t sa = sbase + st * 8192 * 4;
        const unsigned* ga = gA + (size_t)kt * 4096;
        const unsigned* gb = gB + (size_t)kt * 4096;
        #pragma unroll
        for (int i = 0; i < 4; i++)
            cpasync16(sa + (tid + i * 256) * 16, ga + (tid + i * 256) * 4);
        uint32_t sb = sa + 4096 * 4;
        #pragma unroll
        for (int i = 0; i < 4; i++)
            cpasync16(sb + (tid + i * 256) * 16, gb + (tid + i * 256) * 4);
        cp_commit();
    };

    float acc[4][4][4];
    #pragma unroll
    for (int mi = 0; mi < 4; mi++)
        #pragma unroll
        for (int ni = 0; ni < 4; ni++)
            #pragma unroll
            for (int r = 0; r < 4; r++) acc[mi][ni][r] = 0.f;

    issue(0);
    issue(1);

    for (int kt = 0; kt < 32; kt++) {
        if (kt == 31) asm volatile("cp.async.wait_group 0;");
        else          asm volatile("cp.async.wait_group 1;");
        __syncthreads();

        const unsigned* as = sh + (kt % 3) * 8192;
        const unsigned* bs = as + 4096;
        #pragma unroll
        for (int ks = 0; ks < 4; ks++) {
            unsigned af[4][4], bf[4][2];
            #pragma unroll
            for (int mi = 0; mi < 4; mi++) {
                uint4 t = *(const uint4*)(as + ((ks * 8 + wm * 4 + mi) * 32 + lane) * 4);
                af[mi][0] = t.x; af[mi][1] = t.y; af[mi][2] = t.z; af[mi][3] = t.w;
            }
            #pragma unroll
            for (int ni = 0; ni < 4; ni++) {
                uint2 t = *(const uint2*)(bs + ((ks * 16 + wn * 4 + ni) * 32 + lane) * 2);
                bf[ni][0] = t.x; bf[ni][1] = t.y;
            }
            #pragma unroll
            for (int mi = 0; mi < 4; mi++)
                #pragma unroll
                for (int ni = 0; ni < 4; ni++)
                    mma_tf32(acc[mi][ni], af[mi], bf[ni]);
        }

        if (kt + 2 < 32) issue(kt + 2);
    }

    // epilogue + bias
    #pragma unroll
    for (int ni = 0; ni < 4; ni++) {
        int col = n0 + wn * 32 + ni * 8 + 2 * tig;
        float b0 = bias[col], b1 = bias[col + 1];
        #pragma unroll
        for (int mi = 0; mi < 4; mi++) {
            int row = m0 + wm * 64 + mi * 16 + g;
            *(float2*)(C + (size_t)row * Eq + col) =
                make_float2(acc[mi][ni][0] + b0, acc[mi][ni][1] + b1);
            *(float2*)(C + (size_t)(row + 8) * Eq + col) =
                make_float2(acc[mi][ni][2] + b0, acc[mi][ni][3] + b1);
        }
    }
}

// ---------------------------------------------------------------------------
// Flash attention v3 (causal, tf32 MMA). K/V tiles pre-converted fragment
// order in gmem -> 3-stage cp.async. 128 q rows per CTA, 8 warps.
// ---------------------------------------------------------------------------
__global__ void __launch_bounds__(256, 1) attn_tc(
    const float* __restrict__ q, const unsigned* __restrict__ xK,
    const unsigned* __restrict__ vV, float* __restrict__ out)
{
    extern __shared__ unsigned sh[];              // 3 * 8192 uints = 96 KB
    const int tid  = threadIdx.x;
    const int lane = tid & 31;
    const int wid  = tid >> 5;
    const int g    = lane >> 2;
    const int tig  = lane & 3;

    const int qb = (gridDim.x - 1) - blockIdx.x;  // heavy q-blocks first
    const int bh = blockIdx.y;
    const int b  = bh >> 4;
    const int h  = bh & 15;
    const int q0 = qb * 128;

    const float* qbase = q   + ((size_t)(b * Sq + q0)) * Eq + h * Dq;
    float*       obase = out + ((size_t)(b * Sq + q0)) * Eq + h * Dq;
    const unsigned* ktiles = xK + ((size_t)bh * 32) * 4096;
    const unsigned* vtiles = vV + ((size_t)bh * 32) * 4096;
    const uint32_t sbase = (uint32_t)__cvta_generic_to_shared(sh);

    const int NT = 2 * qb + 2;

    auto issue = [&](int kt) {
        int st = kt % 3;
        uint32_t sk = sbase + st * 8192 * 4;
        const unsigned* gk = ktiles + (size_t)kt * 4096;
        const unsigned* gv = vtiles + (size_t)kt * 4096;
        #pragma unroll
        for (int i = 0; i < 4; i++)
            cpasync16(sk + (tid + i * 256) * 16, gk + (tid + i * 256) * 4);
        uint32_t sv = sk + 4096 * 4;
        #pragma unroll
        for (int i = 0; i < 4; i++)
            cpasync16(sv + (tid + i * 256) * 16, gv + (tid + i * 256) * 4);
        cp_commit();
    };

    issue(0);
    issue(1);

    // Q fragments (scaled by 1/sqrt(D) before tf32 rounding)
    unsigned qa[8][4];
    {
        const float* qr0 = qbase + (size_t)(wid * 16 + g) * Eq;
        const float* qr1 = qr0 + (size_t)8 * Eq;
        #pragma unroll
        for (int ks = 0; ks < 8; ks++) {
            int c = ks * 8 + tig;
            qa[ks][0] = f2tf(qr0[c]     * 0.125f);
            qa[ks][1] = f2tf(qr1[c]     * 0.125f);
            qa[ks][2] = f2tf(qr0[c + 4] * 0.125f);
            qa[ks][3] = f2tf(qr1[c + 4] * 0.125f);
        }
    }

    float o[8][4];
    #pragma unroll
    for (int nf = 0; nf < 8; nf++)
        #pragma unroll
        for (int r = 0; r < 4; r++) o[nf][r] = 0.f;

    float m0v = -1e30f, m1v = -1e30f, l0 = 0.f, l1 = 0.f;
    const int row0 = q0 + wid * 16 + g;

    for (int kt = 0; kt < NT; kt++) {
        const int k0 = kt * 64;
        if (kt == NT - 1) asm volatile("cp.async.wait_group 0;");
        else              asm volatile("cp.async.wait_group 1;");
        __syncthreads();

        const unsigned* Ks = sh + (kt % 3) * 8192;
        const unsigned* Vs = Ks + 4096;

        // S = Q @ K^T
        float s[8][4];
        #pragma unroll
        for (int nf = 0; nf < 8; nf++)
            #pragma unroll
            for (int r = 0; r < 4; r++) s[nf][r] = 0.f;
        #pragma unroll
        for (int ks = 0; ks < 8; ks++)
            #pragma unroll
            for (int nf = 0; nf < 8; nf++) {
                uint2 bt = *(const uint2*)(Ks + ((ks * 8 + nf) * 32 + lane) * 2);
                unsigned bf[2] = {bt.x, bt.y};
                mma_tf32(s[nf], qa[ks], bf);
            }

        // causal mask (diagonal tiles only)
        if (k0 + 63 > row0) {
            #pragma unroll
            for (int nf = 0; nf < 8; nf++) {
                int col = k0 + nf * 8 + 2 * tig;
                if (col     > row0)     s[nf][0] = -1e30f;
                if (col + 1 > row0)     s[nf][1] = -1e30f;
                if (col     > row0 + 8) s[nf][2] = -1e30f;
                if (col + 1 > row0 + 8) s[nf][3] = -1e30f;
            }
        }

        // online softmax in registers
        float mx0 = -1e30f, mx1 = -1e30f;
        #pragma unroll
        for (int nf = 0; nf < 8; nf++) {
            mx0 = fmaxf(mx0, fmaxf(s[nf][0], s[nf][1]));
            mx1 = fmaxf(mx1, fmaxf(s[nf][2], s[nf][3]));
        }
        mx0 = fmaxf(mx0, __shfl_xor_sync(0xffffffffu, mx0, 1));
        mx0 = fmaxf(mx0, __shfl_xor_sync(0xffffffffu, mx0, 2));
        mx1 = fmaxf(mx1, __shfl_xor_sync(0xffffffffu, mx1, 1));
        mx1 = fmaxf(mx1, __shfl_xor_sync(0xffffffffu, mx1, 2));

        float mn0 = fmaxf(m0v, mx0), mn1 = fmaxf(m1v, mx1);
        float a0 = __expf(m0v - mn0), a1 = __expf(m1v - mn1);
        m0v = mn0; m1v = mn1;

        float sum0 = 0.f, sum1 = 0.f;
        #pragma unroll
        for (int nf = 0; nf < 8; nf++) {
            s[nf][0] = __expf(s[nf][0] - mn0); sum0 += s[nf][0];
            s[nf][1] = __expf(s[nf][1] - mn0); sum0 += s[nf][1];
            s[nf][2] = __expf(s[nf][2] - mn1); sum1 += s[nf][2];
            s[nf][3] = __expf(s[nf][3] - mn1); sum1 += s[nf][3];
        }
        sum0 += __shfl_xor_sync(0xffffffffu, sum0, 1);
        sum0 += __shfl_xor_sync(0xffffffffu, sum0, 2);
        sum1 += __shfl_xor_sync(0xffffffffu, sum1, 1);
        sum1 += __shfl_xor_sync(0xffffffffu, sum1, 2);
        l0 = l0 * a0 + sum0;
        l1 = l1 * a1 + sum1;

        #pragma unroll
        for (int nf = 0; nf < 8; nf++) {
            o[nf][0] *= a0; o[nf][1] *= a0;
            o[nf][2] *= a1; o[nf][3] *= a1;
        }

        // O += P @ V ; P C-frags -> A-frags via shfl
        const int src1 = g * 4 + (tig >> 1);
        const int src2 = src1 + 2;
        #pragma unroll
        for (int ks = 0; ks < 8; ks++) {
            float w0 = __shfl_sync(0xffffffffu, s[ks][0], src1);
            float w1 = __shfl_sync(0xffffffffu, s[ks][1], src1);
            float w2 = __shfl_sync(0xffffffffu, s[ks][2], src1);
            float w3 = __shfl_sync(0xffffffffu, s[ks][3], src1);
            float y0 = __shfl_sync(0xffffffffu, s[ks][0], src2);
            float y1 = __shfl_sync(0xffffffffu, s[ks][1], src2);
            float y2 = __shfl_sync(0xffffffffu, s[ks][2], src2);
            float y3 = __shfl_sync(0xffffffffu, s[ks][3], src2);
            unsigned pa[4];
            pa[0] = f2tf((tig & 1) ? w1 : w0);
            pa[1] = f2tf((tig & 1) ? w3 : w2);
            pa[2] = f2tf((tig & 1) ? y1 : y0);
            pa[3] = f2tf((tig & 1) ? y3 : y2);
            #pragma unroll
            for (int nf = 0; nf < 8; nf++) {
                uint2 bt = *(const uint2*)(Vs + ((ks * 8 + nf) * 32 + lane) * 2);
                unsigned bf[2] = {bt.x, bt.y};
                mma_tf32(o[nf], pa, bf);
            }
        }

        if (kt + 2 < NT) issue(kt + 2);
    }

    // epilogue
    float il0 = 1.f / l0, il1 = 1.f / l1;
    #pragma unroll
    for (int nf = 0; nf < 8; nf++) {
        int col = nf * 8 + 2 * tig;
        float* p0 = obase + (size_t)(wid * 16 + g) * Eq + col;
        float* p1 = p0 + (size_t)8 * Eq;
        *(float2*)p0 = make_float2(o[nf][0] * il0, o[nf][1] * il0);
        *(float2*)p1 = make_float2(o[nf][2] * il1, o[nf][3] * il1);
    }
}

// ---------------------------------------------------------------------------
// Launch
// ---------------------------------------------------------------------------
extern "C" void kernel_launch(void* const* d_in, const int* in_sizes, int n_in,
                              void* d_out, int out_size)
{
    const float* x        = (const float*)d_in[0];
    const float* c_attn_w = (const float*)d_in[1];
    const float* c_attn_b = (const float*)d_in[2];
    const float* c_proj_w = (const float*)d_in[3];
    const float* c_proj_b = (const float*)d_in[4];
    float* out = (float*)d_out;

    float *q1, *q, *v, *att;
    unsigned *xA, *q1A, *attA, *wqB, *wvB, *wkB, *wpB, *xK, *vV;
    cudaGetSymbolAddress((void**)&q1,   g_q1);
    cudaGetSymbolAddress((void**)&q,    g_q);
    cudaGetSymbolAddress((void**)&v,    g_v);
    cudaGetSymbolAddress((void**)&att,  g_att);
    cudaGetSymbolAddress((void**)&xA,   g_xA);
    cudaGetSymbolAddress((void**)&q1A,  g_q1A);
    cudaGetSymbolAddress((void**)&attA, g_attA);
    cudaGetSymbolAddress((void**)&wqB,  g_wqB);
    cudaGetSymbolAddress((void**)&wvB,  g_wvB);
    cudaGetSymbolAddress((void**)&wkB,  g_wkB);
    cudaGetSymbolAddress((void**)&wpB,  g_wpB);
    cudaGetSymbolAddress((void**)&xK,   g_xK);
    cudaGetSymbolAddress((void**)&vV,   g_vV);

    const int pipe_smem = 3 * 8192 * 4;   // 96 KB
    static int attr_set = 0;
    if (!attr_set) {
        cudaFuncSetAttribute(gemm_frag,
                             cudaFuncAttributeMaxDynamicSharedMemorySize, pipe_smem);
        cudaFuncSetAttribute(attn_tc,
                             cudaFuncAttributeMaxDynamicSharedMemorySize, pipe_smem);
        attr_set = 1;
    }

    // --- conversions (weights + x) ---
    convB <<<1024, 256>>>(c_attn_w,            wqB, 3 * Eq);
    convB <<<1024, 256>>>(c_attn_w + 2 * Eq,   wvB, 3 * Eq);
    convBT<<<1024, 256>>>(c_attn_w + Eq,       wkB, 3 * Eq);
    convB <<<1024, 256>>>(c_proj_w,            wpB, Eq);
    convA <<<4096, 256>>>(x, xA);
    convAttnK<<<4096, 256>>>(x, xK);

    dim3 ggrid(Eq / 128, Mq / 128);   // (8, 32)

    // q1 = x @ Wq + bq
    gemm_frag<<<ggrid, 256, pipe_smem>>>(xA, wqB, c_attn_b, q1);
    convA<<<4096, 256>>>(q1, q1A);
    // v = x @ Wv + bv
    gemm_frag<<<ggrid, 256, pipe_smem>>>(xA, wvB, c_attn_b + 2 * Eq, v);
    convAttnV<<<4096, 256>>>(v, vV);
    // q = q1 @ Wk^T + bk
    gemm_frag<<<ggrid, 256, pipe_smem>>>(q1A, wkB, c_attn_b + Eq, q);

    // flash attention (causal)
    dim3 agrid(Sq / 128, Bq * Hq);    // (16, 32)
    attn_tc<<<agrid, 256, pipe_smem>>>(q, xK, vV, att);

    // out = att @ c_proj_w + c_proj_b
    convA<<<4096, 256>>>(att, attA);
    gemm_frag<<<ggrid, 256, pipe_smem>>>(attA, wpB, c_proj_b, out);
}

// round 4
// speedup vs baseline: 6.7452x; 1.1268x over previous
#include <cuda_runtime.h>
#include <cstddef>
#include <cstdint>

// Problem constants
#define Bq   2
#define Sq   2048
#define Eq   1024
#define Hq   16
#define Dq   64
#define Mq   (Bq*Sq)          // 4096

// ---------------------------------------------------------------------------
// Scratch (device globals; no allocations allowed). All tf32 fragment-order.
// ---------------------------------------------------------------------------
__device__ unsigned g_xA  [(size_t)Mq*Eq];    // x   as GEMM-A frags
__device__ unsigned g_q1A [(size_t)Mq*Eq];    // q1  as GEMM-A frags
__device__ unsigned g_attA[(size_t)Mq*Eq];    // att as GEMM-A frags
__device__ unsigned g_qF  [(size_t)Mq*Eq];    // q   as attention-Q frags (pre-scaled)
__device__ unsigned g_xK  [(size_t)Mq*Eq];    // x   as attention-K frags
__device__ unsigned g_vV  [(size_t)Mq*Eq];    // v   as attention-V frags
__device__ unsigned g_wqB [(size_t)Eq*Eq];    // Wq   as GEMM-B frags
__device__ unsigned g_wvB [(size_t)Eq*Eq];    // Wv   as GEMM-B frags
__device__ unsigned g_wkB [(size_t)Eq*Eq];    // Wk^T as GEMM-B frags
__device__ unsigned g_wpB [(size_t)Eq*Eq];    // Wproj as GEMM-B frags

// ---------------------------------------------------------------------------
// helpers
// ---------------------------------------------------------------------------
__device__ __forceinline__ unsigned f2tf(float x) {
    unsigned r;
    asm("cvt.rna.tf32.f32 %0, %1;" : "=r"(r) : "f"(x));
    return r;
}
__device__ __forceinline__ void mma_tf32(float* c, const unsigned* a, const unsigned* b) {
    asm volatile(
        "mma.sync.aligned.m16n8k8.row.col.f32.tf32.tf32.f32 "
        "{%0,%1,%2,%3}, {%4,%5,%6,%7}, {%8,%9}, {%0,%1,%2,%3};"
        : "+f"(c[0]), "+f"(c[1]), "+f"(c[2]), "+f"(c[3])
        : "r"(a[0]), "r"(a[1]), "r"(a[2]), "r"(a[3]),
          "r"(b[0]), "r"(b[1]));
}
__device__ __forceinline__ void cpasync16(uint32_t s, const void* g) {
    asm volatile("cp.async.cg.shared.global [%0], [%1], 16;" :: "r"(s), "l"(g));
}
__device__ __forceinline__ void cp_commit() {
    asm volatile("cp.async.commit_group;");
}

// ---------------------------------------------------------------------------
// Fragment-store helpers (layouts identical to round-3 validated formulas)
// ---------------------------------------------------------------------------
// GEMM-A-frag: tile=(row>>7)*32+(k>>5), tile size 4096
__device__ __forceinline__ void store_Afrag(unsigned* C, int row, int k, float val) {
    size_t tile = (size_t)(row >> 7) * 32 + (k >> 5);
    int m = row & 127;
    int inner = ((((k >> 3) & 3) * 8 + (m >> 4)) * 32 + (m & 7) * 4 + (k & 3)) * 4
              + (((m & 15) >= 8) ? 1 : 0) + (((k & 7) >= 4) ? 2 : 0);
    C[tile * 4096 + inner] = f2tf(val);
}
// attention V-frag: tile=((b*16+h)*32+kt), tile size 4096
__device__ __forceinline__ void store_Vfrag(unsigned* C, int row, int col, float val) {
    int b = row >> 11, s = row & 2047, kt = s >> 6, kp = s & 63;
    int h = col >> 6, d = col & 63;
    size_t tile = (size_t)((b << 4) + h) * 32 + kt;
    int inner = (((kp >> 3) * 8 + (d >> 3)) * 32 + (d & 7) * 4 + (kp & 3)) * 2
              + (((kp & 7) >= 4) ? 1 : 0);
    C[tile * 4096 + inner] = f2tf(val);
}
// attention Q-frag (pre-scaled by 0.125): tile=((b*16+h)*16+qt), tile size 8192
__device__ __forceinline__ void store_Qfrag(unsigned* C, int row, int col, float val) {
    int b = row >> 11, s = row & 2047, qt = s >> 7, sr = s & 127;
    int h = col >> 6, d = col & 63;
    size_t tile = (size_t)((b << 4) + h) * 16 + qt;
    int inner = (((d >> 3) * 8 + (sr >> 4)) * 32 + (sr & 7) * 4 + (d & 3)) * 4
              + (((sr & 15) >= 8) ? 1 : 0) + (((d & 7) >= 4) ? 2 : 0);
    C[tile * 8192 + inner] = f2tf(val * 0.125f);
}

// ---------------------------------------------------------------------------
// Weight conversion (all 4 weights in one launch). grid = 4*1024 blocks x 256.
// B-frag tile (32k x 128n): idx = ((ks*16+nf)*32 + ln)*2 + rg, 4096 uints.
// ---------------------------------------------------------------------------
__device__ __forceinline__ void convB_body(const float* B, unsigned* dst, int ldb, int idx)
{
    int k  = idx >> 8;
    int n4 = (idx & 255) << 2;
    float4 t = *(const float4*)(B + (size_t)k * ldb + n4);
    float tv[4] = {t.x, t.y, t.z, t.w};
    int ks = (k >> 3) & 3, klo = k & 7;
    int rg = (klo >= 4) ? 1 : 0;
    #pragma unroll
    for (int j = 0; j < 4; j++) {
        int n = n4 + j;
        unsigned* tile = dst + ((size_t)(n >> 7) * 32 + (k >> 5)) * 4096;
        tile[((ks * 16 + ((n >> 3) & 15)) * 32 + (n & 7) * 4 + (klo & 3)) * 2 + rg]
            = f2tf(tv[j]);
    }
}
__device__ __forceinline__ void convBT_body(const float* B, unsigned* dst, int ldb, int idx)
{
    int n  = idx >> 8;
    int k4 = (idx & 255) << 2;
    float4 t = *(const float4*)(B + (size_t)n * ldb + k4);
    float tv[4] = {t.x, t.y, t.z, t.w};
    int nf = (n >> 3) & 15;
    int lpart = (n & 7) * 4;
    #pragma unroll
    for (int j = 0; j < 4; j++) {
        int k = k4 + j;
        int ks = (k >> 3) & 3, klo = k & 7;
        unsigned* tile = dst + ((size_t)(n >> 7) * 32 + (k >> 5)) * 4096;
        tile[((ks * 16 + nf) * 32 + lpart + (klo & 3)) * 2 + ((klo >= 4) ? 1 : 0)]
            = f2tf(tv[j]);
    }
}
__global__ void convW(const float* __restrict__ aw, const float* __restrict__ pw,
                      unsigned* __restrict__ wq, unsigned* __restrict__ wv,
                      unsigned* __restrict__ wk, unsigned* __restrict__ wp)
{
    int which = blockIdx.x >> 10;
    int idx = (blockIdx.x & 1023) * 256 + threadIdx.x;
    if      (which == 0) convB_body (aw,          wq, 3 * Eq, idx);
    else if (which == 1) convB_body (aw + 2 * Eq, wv, 3 * Eq, idx);
    else if (which == 2) convBT_body(aw + Eq,     wk, 3 * Eq, idx);
    else                 convB_body (pw,          wp, Eq,     idx);
}

// ---------------------------------------------------------------------------
// x conversion: one read, two fragment-order writes (GEMM-A + attention-K)
// ---------------------------------------------------------------------------
__global__ void convX(const float* __restrict__ x,
                      unsigned* __restrict__ xA, unsigned* __restrict__ xK)
{
    int idx = blockIdx.x * 256 + threadIdx.x;
    int m   = idx >> 8;                 // global row 0..4095
    int e4  = (idx & 255) << 2;
    float4 t = *(const float4*)(x + (size_t)m * Eq + e4);
    float tv[4] = {t.x, t.y, t.z, t.w};

    // GEMM-A frag
    #pragma unroll
    for (int j = 0; j < 4; j++) store_Afrag(xA, m, e4 + j, tv[j]);

    // attention-K frag
    int s = m & (Sq - 1), b = m >> 11;
    int h = e4 >> 6, d4 = e4 & 63;
    int kt = s >> 6, kp = s & 63;
    unsigned* tile = xK + (((size_t)((b << 4) + h)) * 32 + kt) * 4096;
    #pragma unroll
    for (int j = 0; j < 4; j++) {
        int d = d4 + j;
        tile[(((d >> 3) * 8 + (kp >> 3)) * 32 + (kp & 7) * 4 + (d & 3)) * 2
             + (((d & 7) >= 4) ? 1 : 0)] = f2tf(tv[j]);
    }
}

// ---------------------------------------------------------------------------
// GEMM: C[4096,1024] = Afrag @ Bfrag (+bias). 128x128x32 tiles, 3-stage
// cp.async pipeline. Epilogue MODE: 0=fp32 row-major, 1=A-frag, 2=V-frag,
// 3=Q-frag (scaled).
// ---------------------------------------------------------------------------
template<int MODE>
__global__ void __launch_bounds__(256, 2) gemm_frag(
    const unsigned* __restrict__ Afrag, const unsigned* __restrict__ Bfrag,
    const float* __restrict__ bias, void* __restrict__ Cv)
{
    extern __shared__ unsigned sh[];              // 3 * 8192 uints = 96 KB
    const int tid  = threadIdx.x;
    const int lane = tid & 31;
    const int wid  = tid >> 5;
    const int wm   = wid & 1;
    const int wn   = wid >> 1;
    const int g    = lane >> 2;
    const int tig  = lane & 3;
    const int m0   = blockIdx.y * 128;
    const int n0   = blockIdx.x * 128;

    const unsigned* gA = Afrag + (size_t)blockIdx.y * 32 * 4096;
    const unsigned* gB = Bfrag + (size_t)blockIdx.x * 32 * 4096;
    const uint32_t sbase = (uint32_t)__cvta_generic_to_shared(sh);

    auto issue = [&](int kt) {
        int st = kt % 3;
        uint32_t sa = sbase + st * 8192 * 4;
        const unsigned* ga = gA + (size_t)kt * 4096;
        const unsigned* gb = gB + (size_t)kt * 4096;
        #pragma unroll
        for (int i = 0; i < 4; i++)
            cpasync16(sa + (tid + i * 256) * 16, ga + (tid + i * 256) * 4);
        uint32_t sb = sa + 4096 * 4;
        #pragma unroll
        for (int i = 0; i < 4; i++)
            cpasync16(sb + (tid + i * 256) * 16, gb + (tid + i * 256) * 4);
        cp_commit();
    };

    float acc[4][4][4];
    #pragma unroll
    for (int mi = 0; mi < 4; mi++)
        #pragma unroll
        for (int ni = 0; ni < 4; ni++)
            #pragma unroll
            for (int r = 0; r < 4; r++) acc[mi][ni][r] = 0.f;

    issue(0);
    issue(1);

    for (int kt = 0; kt < 32; kt++) {
        if (kt == 31) asm volatile("cp.async.wait_group 0;");
        else          asm volatile("cp.async.wait_group 1;");
        __syncthreads();

        const unsigned* as = sh + (kt % 3) * 8192;
        const unsigned* bs = as + 4096;
        #pragma unroll
        for (int ks = 0; ks < 4; ks++) {
            unsigned af[4][4], bf[4][2];
            #pragma unroll
            for (int mi = 0; mi < 4; mi++) {
                uint4 t = *(const uint4*)(as + ((ks * 8 + wm * 4 + mi) * 32 + lane) * 4);
                af[mi][0] = t.x; af[mi][1] = t.y; af[mi][2] = t.z; af[mi][3] = t.w;
            }
            #pragma unroll
            for (int ni = 0; ni < 4; ni++) {
                uint2 t = *(const uint2*)(bs + ((ks * 16 + wn * 4 + ni) * 32 + lane) * 2);
                bf[ni][0] = t.x; bf[ni][1] = t.y;
            }
            #pragma unroll
            for (int mi = 0; mi < 4; mi++)
                #pragma unroll
                for (int ni = 0; ni < 4; ni++)
                    mma_tf32(acc[mi][ni], af[mi], bf[ni]);
        }

        if (kt + 2 < 32) issue(kt + 2);
    }

    // epilogue + bias
    #pragma unroll
    for (int ni = 0; ni < 4; ni++) {
        int col = n0 + wn * 32 + ni * 8 + 2 * tig;
        float b0 = bias[col], b1 = bias[col + 1];
        #pragma unroll
        for (int mi = 0; mi < 4; mi++) {
            int row = m0 + wm * 64 + mi * 16 + g;
            if (MODE == 0) {
                float* C = (float*)Cv;
                *(float2*)(C + (size_t)row * Eq + col) =
                    make_float2(acc[mi][ni][0] + b0, acc[mi][ni][1] + b1);
                *(float2*)(C + (size_t)(row + 8) * Eq + col) =
                    make_float2(acc[mi][ni][2] + b0, acc[mi][ni][3] + b1);
            } else {
                unsigned* C = (unsigned*)Cv;
                if (MODE == 1) {
                    store_Afrag(C, row,     col,     acc[mi][ni][0] + b0);
                    store_Afrag(C, row,     col + 1, acc[mi][ni][1] + b1);
                    store_Afrag(C, row + 8, col,     acc[mi][ni][2] + b0);
                    store_Afrag(C, row + 8, col + 1, acc[mi][ni][3] + b1);
                } else if (MODE == 2) {
                    store_Vfrag(C, row,     col,     acc[mi][ni][0] + b0);
                    store_Vfrag(C, row,     col + 1, acc[mi][ni][1] + b1);
                    store_Vfrag(C, row + 8, col,     acc[mi][ni][2] + b0);
                    store_Vfrag(C, row + 8, col + 1, acc[mi][ni][3] + b1);
                } else {
                    store_Qfrag(C, row,     col,     acc[mi][ni][0] + b0);
                    store_Qfrag(C, row,     col + 1, acc[mi][ni][1] + b1);
                    store_Qfrag(C, row + 8, col,     acc[mi][ni][2] + b0);
                    store_Qfrag(C, row + 8, col + 1, acc[mi][ni][3] + b1);
                }
            }
        }
    }
}

// ---------------------------------------------------------------------------
// Flash attention (causal, tf32 MMA). Q pre-fragmented+pre-scaled in gmem;
// K/V fragment-order via 3-stage cp.async; output written as GEMM-A frags.
// 128 q rows per CTA, 8 warps.
// ---------------------------------------------------------------------------
__global__ void __launch_bounds__(256, 1) attn_tc(
    const unsigned* __restrict__ qF, const unsigned* __restrict__ xK,
    const unsigned* __restrict__ vV, unsigned* __restrict__ attA)
{
    extern __shared__ unsigned sh[];              // 3 * 8192 uints = 96 KB
    const int tid  = threadIdx.x;
    const int lane = tid & 31;
    const int wid  = tid >> 5;
    const int g    = lane >> 2;
    const int tig  = lane & 3;

    const int qb = (gridDim.x - 1) - blockIdx.x;  // heavy q-blocks first
    const int bh = blockIdx.y;
    const int b  = bh >> 4;
    const int h  = bh & 15;
    const int q0 = qb * 128;

    const unsigned* ktiles = xK + ((size_t)bh * 32) * 4096;
    const unsigned* vtiles = vV + ((size_t)bh * 32) * 4096;
    const unsigned* qtile  = qF + ((size_t)(bh * 16 + qb)) * 8192;
    unsigned* abase = attA + ((size_t)(b * 16 + qb) * 32) * 4096;
    const uint32_t sbase = (uint32_t)__cvta_generic_to_shared(sh);

    const int NT = 2 * qb + 2;

    auto issue = [&](int kt) {
        int st = kt % 3;
        uint32_t sk = sbase + st * 8192 * 4;
        const unsigned* gk = ktiles + (size_t)kt * 4096;
        const unsigned* gv = vtiles + (size_t)kt * 4096;
        #pragma unroll
        for (int i = 0; i < 4; i++)
            cpasync16(sk + (tid + i * 256) * 16, gk + (tid + i * 256) * 4);
        uint32_t sv = sk + 4096 * 4;
        #pragma unroll
        for (int i = 0; i < 4; i++)
            cpasync16(sv + (tid + i * 256) * 16, gv + (tid + i * 256) * 4);
        cp_commit();
    };

    issue(0);
    issue(1);

    // Q fragments: direct uint4 loads (pre-scaled tf32)
    unsigned qa[8][4];
    #pragma unroll
    for (int ks = 0; ks < 8; ks++) {
        uint4 t = *(const uint4*)(qtile + ((ks * 8 + wid) * 32 + lane) * 4);
        qa[ks][0] = t.x; qa[ks][1] = t.y; qa[ks][2] = t.z; qa[ks][3] = t.w;
    }

    float o[8][4];
    #pragma unroll
    for (int nf = 0; nf < 8; nf++)
        #pragma unroll
        for (int r = 0; r < 4; r++) o[nf][r] = 0.f;

    float m0v = -1e30f, m1v = -1e30f, l0 = 0.f, l1 = 0.f;
    const int row0 = q0 + wid * 16 + g;

    for (int kt = 0; kt < NT; kt++) {
        const int k0 = kt * 64;
        if (kt == NT - 1) asm volatile("cp.async.wait_group 0;");
        else              asm volatile("cp.async.wait_group 1;");
        __syncthreads();

        const unsigned* Ks = sh + (kt % 3) * 8192;
        const unsigned* Vs = Ks + 4096;

        // S = Q @ K^T
        float s[8][4];
        #pragma unroll
        for (int nf = 0; nf < 8; nf++)
            #pragma unroll
            for (int r = 0; r < 4; r++) s[nf][r] = 0.f;
        #pragma unroll
        for (int ks = 0; ks < 8; ks++)
            #pragma unroll
            for (int nf = 0; nf < 8; nf++) {
                uint2 bt = *(const uint2*)(Ks + ((ks * 8 + nf) * 32 + lane) * 2);
                unsigned bf[2] = {bt.x, bt.y};
                mma_tf32(s[nf], qa[ks], bf);
            }

        // causal mask (diagonal tiles only)
        if (k0 + 63 > row0) {
            #pragma unroll
            for (int nf = 0; nf < 8; nf++) {
                int col = k0 + nf * 8 + 2 * tig;
                if (col     > row0)     s[nf][0] = -1e30f;
                if (col + 1 > row0)     s[nf][1] = -1e30f;
                if (col     > row0 + 8) s[nf][2] = -1e30f;
                if (col + 1 > row0 + 8) s[nf][3] = -1e30f;
            }
        }

        // online softmax in registers
        float mx0 = -1e30f, mx1 = -1e30f;
        #pragma unroll
        for (int nf = 0; nf < 8; nf++) {
            mx0 = fmaxf(mx0, fmaxf(s[nf][0], s[nf][1]));
            mx1 = fmaxf(mx1, fmaxf(s[nf][2], s[nf][3]));
        }
        mx0 = fmaxf(mx0, __shfl_xor_sync(0xffffffffu, mx0, 1));
        mx0 = fmaxf(mx0, __shfl_xor_sync(0xffffffffu, mx0, 2));
        mx1 = fmaxf(mx1, __shfl_xor_sync(0xffffffffu, mx1, 1));
        mx1 = fmaxf(mx1, __shfl_xor_sync(0xffffffffu, mx1, 2));

        float mn0 = fmaxf(m0v, mx0), mn1 = fmaxf(m1v, mx1);
        float a0 = __expf(m0v - mn0), a1 = __expf(m1v - mn1);
        m0v = mn0; m1v = mn1;

        float sum0 = 0.f, sum1 = 0.f;
        #pragma unroll
        for (int nf = 0; nf < 8; nf++) {
            s[nf][0] = __expf(s[nf][0] - mn0); sum0 += s[nf][0];
            s[nf][1] = __expf(s[nf][1] - mn0); sum0 += s[nf][1];
            s[nf][2] = __expf(s[nf][2] - mn1); sum1 += s[nf][2];
            s[nf][3] = __expf(s[nf][3] - mn1); sum1 += s[nf][3];
        }
        sum0 += __shfl_xor_sync(0xffffffffu, sum0, 1);
        sum0 += __shfl_xor_sync(0xffffffffu, sum0, 2);
        sum1 += __shfl_xor_sync(0xffffffffu, sum1, 1);
        sum1 += __shfl_xor_sync(0xffffffffu, sum1, 2);
        l0 = l0 * a0 + sum0;
        l1 = l1 * a1 + sum1;

        #pragma unroll
        for (int nf = 0; nf < 8; nf++) {
            o[nf][0] *= a0; o[nf][1] *= a0;
            o[nf][2] *= a1; o[nf][3] *= a1;
        }

        // O += P @ V ; P C-frags -> A-frags via shfl
        const int src1 = g * 4 + (tig >> 1);
        const int src2 = src1 + 2;
        #pragma unroll
        for (int ks = 0; ks < 8; ks++) {
            float w0 = __shfl_sync(0xffffffffu, s[ks][0], src1);
            float w1 = __shfl_sync(0xffffffffu, s[ks][1], src1);
            float w2 = __shfl_sync(0xffffffffu, s[ks][2], src1);
            float w3 = __shfl_sync(0xffffffffu, s[ks][3], src1);
            float y0 = __shfl_sync(0xffffffffu, s[ks][0], src2);
            float y1 = __shfl_sync(0xffffffffu, s[ks][1], src2);
            float y2 = __shfl_sync(0xffffffffu, s[ks][2], src2);
            float y3 = __shfl_sync(0xffffffffu, s[ks][3], src2);
            unsigned pa[4];
            pa[0] = f2tf((tig & 1) ? w1 : w0);
            pa[1] = f2tf((tig & 1) ? w3 : w2);
            pa[2] = f2tf((tig & 1) ? y1 : y0);
            pa[3] = f2tf((tig & 1) ? y3 : y2);
            #pragma unroll
            for (int nf = 0; nf < 8; nf++) {
                uint2 bt = *(const uint2*)(Vs + ((ks * 8 + nf) * 32 + lane) * 2);
                unsigned bf[2] = {bt.x, bt.y};
                mma_tf32(o[nf], pa, bf);
            }
        }

        if (kt + 2 < NT) issue(kt + 2);
    }

    // epilogue: normalize, write directly as GEMM-A frags for the proj GEMM
    float il0 = 1.f / l0, il1 = 1.f / l1;
    const int mr0 = wid * 16 + g, mr1 = mr0 + 8;
    #pragma unroll
    for (int nf = 0; nf < 8; nf++) {
        int e = h * 64 + nf * 8 + 2 * tig;
        #pragma unroll
        for (int rr = 0; rr < 2; rr++) {
            int ee = e + rr;
            int base_inner = ((((ee >> 3) & 3) * 8) * 32 + (ee & 3)) * 4
                           + (((ee & 7) >= 4) ? 2 : 0);
            unsigned* tp = abase + (size_t)(ee >> 5) * 4096;
            // row mr0
            tp[base_inner + ((mr0 >> 4) * 32 + (mr0 & 7) * 4) * 4
               + (((mr0 & 15) >= 8) ? 1 : 0)] = f2tf(o[nf][rr]     * il0);
            // row mr1
            tp[base_inner + ((mr1 >> 4) * 32 + (mr1 & 7) * 4) * 4
               + (((mr1 & 15) >= 8) ? 1 : 0)] = f2tf(o[nf][2 + rr] * il1);
        }
    }
}

// ---------------------------------------------------------------------------
// Launch
// ---------------------------------------------------------------------------
extern "C" void kernel_launch(void* const* d_in, const int* in_sizes, int n_in,
                              void* d_out, int out_size)
{
    const float* x        = (const float*)d_in[0];
    const float* c_attn_w = (const float*)d_in[1];
    const float* c_attn_b = (const float*)d_in[2];
    const float* c_proj_w = (const float*)d_in[3];
    const float* c_proj_b = (const float*)d_in[4];
    float* out = (float*)d_out;

    unsigned *xA, *q1A, *attA, *qF, *xK, *vV, *wqB, *wvB, *wkB, *wpB;
    cudaGetSymbolAddress((void**)&xA,   g_xA);
    cudaGetSymbolAddress((void**)&q1A,  g_q1A);
    cudaGetSymbolAddress((void**)&attA, g_attA);
    cudaGetSymbolAddress((void**)&qF,   g_qF);
    cudaGetSymbolAddress((void**)&xK,   g_xK);
    cudaGetSymbolAddress((void**)&vV,   g_vV);
    cudaGetSymbolAddress((void**)&wqB,  g_wqB);
    cudaGetSymbolAddress((void**)&wvB,  g_wvB);
    cudaGetSymbolAddress((void**)&wkB,  g_wkB);
    cudaGetSymbolAddress((void**)&wpB,  g_wpB);

    const int pipe_smem = 3 * 8192 * 4;   // 96 KB
    static int attr_set = 0;
    if (!attr_set) {
        cudaFuncSetAttribute(gemm_frag<0>,
                             cudaFuncAttributeMaxDynamicSharedMemorySize, pipe_smem);
        cudaFuncSetAttribute(gemm_frag<1>,
                             cudaFuncAttributeMaxDynamicSharedMemorySize, pipe_smem);
        cudaFuncSetAttribute(gemm_frag<2>,
                             cudaFuncAttributeMaxDynamicSharedMemorySize, pipe_smem);
        cudaFuncSetAttribute(gemm_frag<3>,
                             cudaFuncAttributeMaxDynamicSharedMemorySize, pipe_smem);
        cudaFuncSetAttribute(attn_tc,
                             cudaFuncAttributeMaxDynamicSharedMemorySize, pipe_smem);
        attr_set = 1;
    }

    // conversions: weights (one launch) + x (one launch)
    convW<<<4096, 256>>>(c_attn_w, c_proj_w, wqB, wvB, wkB, wpB);
    convX<<<4096, 256>>>(x, xA, xK);

    dim3 ggrid(Eq / 128, Mq / 128);   // (8, 32)

    // q1 = x @ Wq + bq          -> GEMM-A frags
    gemm_frag<1><<<ggrid, 256, pipe_smem>>>(xA, wqB, c_attn_b, q1A);
    // v = x @ Wv + bv           -> attention V frags
    gemm_frag<2><<<ggrid, 256, pipe_smem>>>(xA, wvB, c_attn_b + 2 * Eq, vV);
    // q = q1 @ Wk^T + bk        -> attention Q frags (pre-scaled)
    gemm_frag<3><<<ggrid, 256, pipe_smem>>>(q1A, wkB, c_attn_b + Eq, qF);

    // flash attention (causal)  -> GEMM-A frags
    dim3 agrid(Sq / 128, Bq * Hq);    // (16, 32)
    attn_tc<<<agrid, 256, pipe_smem>>>(qF, xK, vV, attA);

    // out = att @ Wproj + bproj -> fp32
    gemm_frag<0><<<ggrid, 256, pipe_smem>>>(attA, wpB, c_proj_b, out);
}